// round 14
// baseline (speedup 1.0000x reference)
#include <cuda_runtime.h>
#include <cuda_fp16.h>
#include <cstdint>

// ============================================================================
// SharedMatrix (butterfly block-sparse matmul) on GB300, PLAIN sm_103 target.
//   x : [8192, 4096] f32          (d_in[0])
//   w : [4096, 5, 256] f32        (d_in[1])
//   fi: [16, 5] int32             (d_in[2])
//   out:[8192, 4096] f32
//
// 16 GEMMs: M=8192, N=256, K=1280, fp16 mma.sync.m16n8k16 (f32 accum).
// R14 vs R13: persistent CTAs (grid = #SMs), cp.async 4-stage ring runs
// continuously ACROSS tile boundaries (kills 6/7 cold prologues, hides
// epilogue under next tile's prefetch); mma(ks2) hoisted before the
// cp_wait+barrier so the barrier sits under a queued MMA group.
// ============================================================================

static constexpr int NKIT = 20;                    // 5 blocks x 4 chunks of k=64
static constexpr int NTILES = 1024;                // 16 o x 64 m
static constexpr uint32_t A_BYTES = 16384;         // 128 x 64 x 2
static constexpr uint32_t B_BYTES = 32768;         // 256 x 64 x 2
static constexpr uint32_t STAGE_BYTES = A_BYTES + B_BYTES;      // 48KB
static constexpr uint32_t SMEM_TOTAL = 4 * STAGE_BYTES + 1024;  // 197632

// x converted to fp16 (RN), row-major [8192][4096], packed as uint32 pairs.
__device__ uint32_t g_Xh[8192u * 2048u];           // 64 MB
// Repacked gathered fp16 weights, pre-swizzled 32KB SMEM images:
// image (o, c64): [n=256][k=64] fp16, swz(n*128 + kk*2).  16*20*32KB = 10.5MB
__device__ uint32_t g_Bp[16 * NKIT * 8192];

// ---------------------------------------------------------------------------
__device__ __forceinline__ uint32_t h2_bits(__half2 h) {
    union { __half2 h; uint32_t u; } cvt;
    cvt.h = h;
    return cvt.u;
}
__device__ __forceinline__ uint32_t smem_u32(const void* p) {
    uint32_t a;
    asm("{ .reg .u64 t; cvta.to.shared.u64 t, %1; cvt.u32.u64 %0, t; }"
        : "=r"(a) : "l"(p));
    return a;
}
__device__ __forceinline__ void cpasync16(uint32_t dst, const void* src) {
    asm volatile("cp.async.cg.shared.global [%0], [%1], 16;"
                 :: "r"(dst), "l"(src) : "memory");
}
__device__ __forceinline__ void cp_commit() {
    asm volatile("cp.async.commit_group;" ::: "memory");
}
template <int N>
__device__ __forceinline__ void cp_wait() {
    asm volatile("cp.async.wait_group %0;" :: "n"(N) : "memory");
}
__device__ __forceinline__ void ldsm4(uint32_t* r, uint32_t a) {
    asm volatile("ldmatrix.sync.aligned.m8n8.x4.shared.b16 {%0,%1,%2,%3}, [%4];"
                 : "=r"(r[0]), "=r"(r[1]), "=r"(r[2]), "=r"(r[3]) : "r"(a));
}
__device__ __forceinline__ void mma_f16(float* c, const uint32_t* a,
                                        uint32_t b0, uint32_t b1) {
    asm volatile(
        "mma.sync.aligned.m16n8k16.row.col.f32.f16.f16.f32 "
        "{%0,%1,%2,%3}, {%4,%5,%6,%7}, {%8,%9}, {%0,%1,%2,%3};"
        : "+f"(c[0]), "+f"(c[1]), "+f"(c[2]), "+f"(c[3])
        : "r"(a[0]), "r"(a[1]), "r"(a[2]), "r"(a[3]), "r"(b0), "r"(b1));
}

// ---------------------------------------------------------------------------
// convert: x f32 -> fp16 (RN) into g_Xh. One block per row of 4096.
// ---------------------------------------------------------------------------
__global__ void __launch_bounds__(256, 4)
convert_kernel(const float* __restrict__ x) {
    const size_t row = blockIdx.x;
    const float4* src = reinterpret_cast<const float4*>(x + row * 4096) +
                        threadIdx.x * 4;
    uint4* dst = reinterpret_cast<uint4*>(g_Xh + row * 2048) +
                 threadIdx.x * 2;
    float4 v0 = src[0], v1 = src[1], v2 = src[2], v3 = src[3];
    uint4 o;
    o.x = h2_bits(__floats2half2_rn(v0.x, v0.y));
    o.y = h2_bits(__floats2half2_rn(v0.z, v0.w));
    o.z = h2_bits(__floats2half2_rn(v1.x, v1.y));
    o.w = h2_bits(__floats2half2_rn(v1.z, v1.w));
    dst[0] = o;
    o.x = h2_bits(__floats2half2_rn(v2.x, v2.y));
    o.y = h2_bits(__floats2half2_rn(v2.z, v2.w));
    o.z = h2_bits(__floats2half2_rn(v3.x, v3.y));
    o.w = h2_bits(__floats2half2_rn(v3.z, v3.w));
    dst[1] = o;
}

// ---------------------------------------------------------------------------
// repack: gather + transpose + fp16(RN) weights into pre-swizzled images
//   grid: (ntile=8, kchunk32=8, o*5+a=80), block (32, 8)
// image (o, c64 = a*4 + (c32>>1)), k base within image = (c32&1)*32
// ---------------------------------------------------------------------------
__global__ void __launch_bounds__(256, 4)
repack_kernel(const float* __restrict__ w, const int* __restrict__ fi) {
    const int oa = blockIdx.z;
    const int o = oa / 5, a = oa % 5;
    const int f = fi[o * 5 + a];
    const int g = f / 5, slot = f % 5;
    const int k0 = blockIdx.y * 32;
    const int n0 = blockIdx.x * 32;
    const int c32 = blockIdx.y;

    __shared__ float t[32][33];
    const int tx = threadIdx.x, ty = threadIdx.y;

    #pragma unroll
    for (int i = 0; i < 4; ++i) {
        int k = ty + i * 8;
        t[k][tx] = w[((size_t)(g * 256 + k0 + k) * 5 + slot) * 256 + n0 + tx];
    }
    __syncthreads();

    uint32_t* tile = g_Bp +
        ((size_t)o * NKIT + a * 4 + (c32 >> 1)) * 8192;
    const int kb = (c32 & 1) * 32;
    const int tid = ty * 32 + tx;
    const int p  = tid & 15;        // k pair index 0..15 (2 fp16 each)
    const int nn = tid >> 4;        // 0..15
    #pragma unroll
    for (int i = 0; i < 2; ++i) {
        int n = n0 + nn + i * 16;
        uint32_t val = h2_bits(
            __floats2half2_rn(t[2 * p][nn + i * 16], t[2 * p + 1][nn + i * 16]));
        uint32_t off = (uint32_t)n * 128u + (uint32_t)(kb + 2 * p) * 2u;
        uint32_t swz = off ^ ((off >> 3) & 0x70u);
        tile[swz >> 2] = val;
    }
}

// ---------------------------------------------------------------------------
// GEMM: persistent, grid = #SMs, 256 threads, tile = 128(M) x 256(N).
//   8 warps in 2(m) x 4(n) grid of 64x64 warp tiles; fp16 m16n8k16;
//   4-stage cp.async ring continuous across tiles.
// tile id t in [0,1024): o = t & 15, m_base = (t >> 4) * 128.
// ---------------------------------------------------------------------------
__global__ void __launch_bounds__(256, 1)
gemm_kernel(const int* __restrict__ fi, float* __restrict__ out) {
    extern __shared__ char smem_raw[];
    __shared__ int colf_s[80];
    const uint32_t sb = (smem_u32(smem_raw) + 1023u) & ~1023u;
    const int tid = (int)threadIdx.x;
    const int wid = tid >> 5;
    const int lane = tid & 31;
    const int warp_m = wid >> 2;   // 0..1  (64 rows each)
    const int warp_n = wid & 3;    // 0..3  (64 cols each)
    const int step = (int)gridDim.x;

    if (tid < 80) colf_s[tid] = (fi[tid] / 5) << 8;   // fp16 col base
    __syncthreads();

    // ---- producer addressing (all 256 threads) ----
    const int arow = tid >> 1;                 // 0..127
    const int asub = (tid & 1) * 4;            // segments asub..asub+3 (of 8)
    const uint32_t adst_base = (uint32_t)arow * 128u;
    const uint32_t axor = (uint32_t)(arow & 7) << 4;

    // issue-head cursor: next (tile, it) to prefetch; stage = head_it & 3
    int head_tile = (int)blockIdx.x;
    int head_it = 0;

    auto issue_head = [&]() {
        if (head_tile < NTILES) {
            const uint32_t st = sb + (uint32_t)(head_it & 3) * STAGE_BYTES;
            const int o_h = head_tile & 15;
            const int mb_h = (head_tile >> 4) * 128;
            const int col = colf_s[o_h * 5 + (head_it >> 2)] +
                            (head_it & 3) * 64;           // fp16 col
            const uint32_t* asrc = g_Xh + (size_t)(mb_h + arow) * 2048 +
                                   (col >> 1) + asub * 4;
            #pragma unroll
            for (int j = 0; j < 4; ++j) {
                uint32_t doff = (((uint32_t)(asub + j) * 16u) ^ axor);
                cpasync16(st + adst_base + doff, asrc + j * 4);
            }
            const uint32_t* bsrc = g_Bp +
                ((size_t)o_h * NKIT + head_it) * 8192 + tid * 4;
            #pragma unroll
            for (int j = 0; j < 8; ++j)
                cpasync16(st + A_BYTES + (uint32_t)tid * 16u +
                          (uint32_t)j * 4096u, bsrc + j * 1024);
        }
        cp_commit();
        if (++head_it == NKIT) { head_it = 0; head_tile += step; }
    };

    // ---- consumer lane addressing ----
    const int a_tile = lane >> 3;              // 0..3
    const int a_row_l = ((a_tile & 1) << 3) + (lane & 7);
    const int a_ktile = a_tile >> 1;           // 0..1 (16B half of 32B k-step)
    const int b_khalf = (lane >> 3) & 1;
    const int b_row_l = (((lane >> 4) & 1) << 3) + (lane & 7);

    const uint32_t a_warp_off = (uint32_t)(warp_m * 64) * 128u;
    const uint32_t b_warp_off = A_BYTES + (uint32_t)(warp_n * 64) * 128u;

    float c[4][8][4];
    uint32_t af[2][4][4];   // [pingpong][mi][frag]
    uint32_t bf[2][4][4];   // [pingpong][ni2][frag]

    auto load_frags = [&](uint32_t st, int ks, int pb) {
        const uint32_t abw = st + a_warp_off;
        const uint32_t bbw = st + b_warp_off;
        #pragma unroll
        for (int mi = 0; mi < 4; ++mi) {
            int row = mi * 16 + a_row_l;
            uint32_t off = (uint32_t)((ks * 2 + a_ktile) * 16) ^
                           ((uint32_t)(row & 7) << 4);
            ldsm4(af[pb][mi], abw + (uint32_t)row * 128u + off);
        }
        #pragma unroll
        for (int ni2 = 0; ni2 < 4; ++ni2) {
            int n = ni2 * 16 + b_row_l;
            uint32_t off = (uint32_t)((ks * 2 + b_khalf) * 16) ^
                           ((uint32_t)(n & 7) << 4);
            ldsm4(bf[pb][ni2], bbw + (uint32_t)n * 128u + off);
        }
    };

    auto mma_group = [&](int pb) {
        #pragma unroll
        for (int mi = 0; mi < 4; ++mi)
            #pragma unroll
            for (int ni = 0; ni < 8; ++ni) {
                const uint32_t* bp = &bf[pb][ni >> 1][(ni & 1) * 2];
                mma_f16(c[mi][ni], af[pb][mi], bp[0], bp[1]);
            }
    };

    // prologue: prefetch positions 0,1,2 (stages 0,1,2); land frags for ks0
    issue_head(); issue_head(); issue_head();
    cp_wait<2>();
    __syncthreads();
    load_frags(sb, 0, 0);

    const int eg = lane >> 2, et4 = lane & 3;

    for (int cur = (int)blockIdx.x; cur < NTILES; cur += step) {
        #pragma unroll
        for (int mi = 0; mi < 4; ++mi)
            #pragma unroll
            for (int ni = 0; ni < 8; ++ni)
                #pragma unroll
                for (int q = 0; q < 4; ++q) c[mi][ni][q] = 0.0f;

        #pragma unroll 4
        for (int it = 0; it < NKIT; ++it) {
            const uint32_t st = sb + (uint32_t)(it & 3) * STAGE_BYTES;

            // entry invariant: pb0 holds ks0 frags of this stage
            load_frags(st, 1, 1);             // ks1 -> pb1
            mma_group(0);                     // ks0
            issue_head();                     // prefetch position it+3
            load_frags(st, 2, 0);             // ks2 -> pb0
            mma_group(1);                     // ks1
            load_frags(st, 3, 1);             // ks3 -> pb1
            mma_group(0);                     // ks2 (queued under barrier)

            cp_wait<2>();                     // next stage landed
            __syncthreads();

            const uint32_t nst = sb + (uint32_t)((it + 1) & 3) * STAGE_BYTES;
            if (it + 1 < NKIT || cur + step < NTILES)
                load_frags(nst, 0, 0);        // next ks0 -> pb0
            mma_group(1);                     // ks3
        }

        // ---- epilogue: direct stores (prefetch for next tile in flight) ----
        const int o = cur & 15;
        const int row0 = (cur >> 4) * 128 + warp_m * 64 + eg;
        const int col0 = o * 256 + warp_n * 64 + et4 * 2;
        #pragma unroll
        for (int mi = 0; mi < 4; ++mi) {
            #pragma unroll
            for (int ni = 0; ni < 8; ++ni) {
                float* p0 = out + (size_t)(row0 + mi * 16) * 4096 + col0 + ni * 8;
                float* p1 = p0 + 8 * 4096;
                *reinterpret_cast<float2*>(p0) =
                    make_float2(c[mi][ni][0], c[mi][ni][1]);
                *reinterpret_cast<float2*>(p1) =
                    make_float2(c[mi][ni][2], c[mi][ni][3]);
            }
        }
    }
}

// ---------------------------------------------------------------------------
extern "C" void kernel_launch(void* const* d_in, const int* in_sizes, int n_in,
                              void* d_out, int out_size) {
    const float* x  = (const float*)d_in[0];
    const float* w  = (const float*)d_in[1];
    const int*   fi = (const int*)d_in[2];
    float* out = (float*)d_out;

    convert_kernel<<<8192, 256>>>(x);
    repack_kernel<<<dim3(8, 8, 80), dim3(32, 8)>>>(w, fi);

    int sms = 148;
    cudaDeviceGetAttribute(&sms, cudaDevAttrMultiProcessorCount, 0);

    cudaFuncSetAttribute(gemm_kernel,
                         cudaFuncAttributeMaxDynamicSharedMemorySize, SMEM_TOTAL);
    gemm_kernel<<<sms, 256, SMEM_TOTAL>>>(fi, out);
}

// round 15
// speedup vs baseline: 1.0232x; 1.0232x over previous
#include <cuda_runtime.h>
#include <cuda_fp16.h>
#include <cstdint>

// ============================================================================
// SharedMatrix (butterfly block-sparse matmul) on GB300, PLAIN sm_103 target.
//   x : [8192, 4096] f32          (d_in[0])
//   w : [4096, 5, 256] f32        (d_in[1])
//   fi: [16, 5] int32             (d_in[2])
//   out:[8192, 4096] f32
//
// 16 GEMMs: M=8192, N=256, K=1280, fp16 mma.sync.m16n8k16 (f32 accum).
// R15 = R13 shell (non-persistent; persistent was neutral) +
//   (a) mma(ks2) hoisted before cp_wait/barrier (barrier under queued MMA),
//   (b) st.global.cs streaming epilogue (keep B/x hot in L2).
// ============================================================================

static constexpr int NKIT = 20;                    // 5 blocks x 4 chunks of k=64
static constexpr uint32_t A_BYTES = 16384;         // 128 x 64 x 2
static constexpr uint32_t B_BYTES = 32768;         // 256 x 64 x 2
static constexpr uint32_t STAGE_BYTES = A_BYTES + B_BYTES;      // 48KB
static constexpr uint32_t SMEM_TOTAL = 4 * STAGE_BYTES + 1024;  // 197632

// x converted to fp16 (RN), row-major [8192][4096], packed as uint32 pairs.
__device__ uint32_t g_Xh[8192u * 2048u];           // 64 MB
// Repacked gathered fp16 weights, pre-swizzled 32KB SMEM images:
// image (o, c64): [n=256][k=64] fp16, swz(n*128 + kk*2).  16*20*32KB = 10.5MB
__device__ uint32_t g_Bp[16 * NKIT * 8192];

// ---------------------------------------------------------------------------
__device__ __forceinline__ uint32_t h2_bits(__half2 h) {
    union { __half2 h; uint32_t u; } cvt;
    cvt.h = h;
    return cvt.u;
}
__device__ __forceinline__ uint32_t smem_u32(const void* p) {
    uint32_t a;
    asm("{ .reg .u64 t; cvta.to.shared.u64 t, %1; cvt.u32.u64 %0, t; }"
        : "=r"(a) : "l"(p));
    return a;
}
__device__ __forceinline__ void cpasync16(uint32_t dst, const void* src) {
    asm volatile("cp.async.cg.shared.global [%0], [%1], 16;"
                 :: "r"(dst), "l"(src) : "memory");
}
__device__ __forceinline__ void cp_commit() {
    asm volatile("cp.async.commit_group;" ::: "memory");
}
template <int N>
__device__ __forceinline__ void cp_wait() {
    asm volatile("cp.async.wait_group %0;" :: "n"(N) : "memory");
}
__device__ __forceinline__ void ldsm4(uint32_t* r, uint32_t a) {
    asm volatile("ldmatrix.sync.aligned.m8n8.x4.shared.b16 {%0,%1,%2,%3}, [%4];"
                 : "=r"(r[0]), "=r"(r[1]), "=r"(r[2]), "=r"(r[3]) : "r"(a));
}
__device__ __forceinline__ void mma_f16(float* c, const uint32_t* a,
                                        uint32_t b0, uint32_t b1) {
    asm volatile(
        "mma.sync.aligned.m16n8k16.row.col.f32.f16.f16.f32 "
        "{%0,%1,%2,%3}, {%4,%5,%6,%7}, {%8,%9}, {%0,%1,%2,%3};"
        : "+f"(c[0]), "+f"(c[1]), "+f"(c[2]), "+f"(c[3])
        : "r"(a[0]), "r"(a[1]), "r"(a[2]), "r"(a[3]), "r"(b0), "r"(b1));
}
__device__ __forceinline__ void stg_cs_v2(float* p, float v0, float v1) {
    asm volatile("st.global.cs.v2.f32 [%0], {%1, %2};"
                 :: "l"(p), "f"(v0), "f"(v1) : "memory");
}

// ---------------------------------------------------------------------------
// convert: x f32 -> fp16 (RN) into g_Xh. One block per row of 4096.
// ---------------------------------------------------------------------------
__global__ void __launch_bounds__(256, 4)
convert_kernel(const float* __restrict__ x) {
    const size_t row = blockIdx.x;
    const float4* src = reinterpret_cast<const float4*>(x + row * 4096) +
                        threadIdx.x * 4;
    uint4* dst = reinterpret_cast<uint4*>(g_Xh + row * 2048) +
                 threadIdx.x * 2;
    float4 v0 = src[0], v1 = src[1], v2 = src[2], v3 = src[3];
    uint4 o;
    o.x = h2_bits(__floats2half2_rn(v0.x, v0.y));
    o.y = h2_bits(__floats2half2_rn(v0.z, v0.w));
    o.z = h2_bits(__floats2half2_rn(v1.x, v1.y));
    o.w = h2_bits(__floats2half2_rn(v1.z, v1.w));
    dst[0] = o;
    o.x = h2_bits(__floats2half2_rn(v2.x, v2.y));
    o.y = h2_bits(__floats2half2_rn(v2.z, v2.w));
    o.z = h2_bits(__floats2half2_rn(v3.x, v3.y));
    o.w = h2_bits(__floats2half2_rn(v3.z, v3.w));
    dst[1] = o;
}

// ---------------------------------------------------------------------------
// repack: gather + transpose + fp16(RN) weights into pre-swizzled images
//   grid: (ntile=8, kchunk32=8, o*5+a=80), block (32, 8)
// image (o, c64 = a*4 + (c32>>1)), k base within image = (c32&1)*32
// ---------------------------------------------------------------------------
__global__ void __launch_bounds__(256, 4)
repack_kernel(const float* __restrict__ w, const int* __restrict__ fi) {
    const int oa = blockIdx.z;
    const int o = oa / 5, a = oa % 5;
    const int f = fi[o * 5 + a];
    const int g = f / 5, slot = f % 5;
    const int k0 = blockIdx.y * 32;
    const int n0 = blockIdx.x * 32;
    const int c32 = blockIdx.y;

    __shared__ float t[32][33];
    const int tx = threadIdx.x, ty = threadIdx.y;

    #pragma unroll
    for (int i = 0; i < 4; ++i) {
        int k = ty + i * 8;
        t[k][tx] = w[((size_t)(g * 256 + k0 + k) * 5 + slot) * 256 + n0 + tx];
    }
    __syncthreads();

    uint32_t* tile = g_Bp +
        ((size_t)o * NKIT + a * 4 + (c32 >> 1)) * 8192;
    const int kb = (c32 & 1) * 32;
    const int tid = ty * 32 + tx;
    const int p  = tid & 15;        // k pair index 0..15 (2 fp16 each)
    const int nn = tid >> 4;        // 0..15
    #pragma unroll
    for (int i = 0; i < 2; ++i) {
        int n = n0 + nn + i * 16;
        uint32_t val = h2_bits(
            __floats2half2_rn(t[2 * p][nn + i * 16], t[2 * p + 1][nn + i * 16]));
        uint32_t off = (uint32_t)n * 128u + (uint32_t)(kb + 2 * p) * 2u;
        uint32_t swz = off ^ ((off >> 3) & 0x70u);
        tile[swz >> 2] = val;
    }
}

// ---------------------------------------------------------------------------
// GEMM: grid (o=16, mtile=64), 256 threads, CTA tile 128(M) x 256(N)
//   8 warps in 2(m) x 4(n) grid of 64x64 warp tiles; fp16 m16n8k16;
//   k=64 per stage, barrier hidden under queued MMA work.
// ---------------------------------------------------------------------------
__global__ void __launch_bounds__(256, 1)
gemm_kernel(const int* __restrict__ fi, float* __restrict__ out) {
    extern __shared__ char smem_raw[];
    const uint32_t sb = (smem_u32(smem_raw) + 1023u) & ~1023u;
    const int tid = (int)threadIdx.x;
    const int wid = tid >> 5;
    const int lane = tid & 31;
    const int o = (int)blockIdx.x;
    const int m_base = (int)blockIdx.y * 128;
    const int warp_m = wid >> 2;   // 0..1  (64 rows each)
    const int warp_n = wid & 3;    // 0..3  (64 cols each)

    int colf[5];
    #pragma unroll
    for (int a = 0; a < 5; ++a) colf[a] = (fi[o * 5 + a] / 5) << 8;  // fp16 elems

    // ---- producer addressing (all 256 threads) ----
    const int arow = tid >> 1;                 // 0..127
    const int asub = (tid & 1) * 4;            // segments asub..asub+3 (of 8)
    const uint32_t* xrow = g_Xh + (size_t)(m_base + arow) * 2048;
    const uint32_t adst_base = (uint32_t)arow * 128u;
    const uint32_t axor = (uint32_t)(arow & 7) << 4;
    const uint32_t* bsrc0 = g_Bp + (size_t)o * NKIT * 8192 + tid * 4;

    auto issue = [&](int it, uint32_t s) {
        const uint32_t st = sb + s * STAGE_BYTES;
        const int col = colf[it >> 2] + (it & 3) * 64;    // fp16 col
        const uint32_t* asrc = xrow + (col >> 1) + asub * 4;
        #pragma unroll
        for (int j = 0; j < 4; ++j) {
            uint32_t doff = (((uint32_t)(asub + j) * 16u) ^ axor);
            cpasync16(st + adst_base + doff, asrc + j * 4);
        }
        const uint32_t* bsrc = bsrc0 + (size_t)it * 8192;
        #pragma unroll
        for (int j = 0; j < 8; ++j)
            cpasync16(st + A_BYTES + (uint32_t)tid * 16u + (uint32_t)j * 4096u,
                      bsrc + j * 1024);
        cp_commit();
    };

    // ---- consumer lane addressing ----
    const int a_tile = lane >> 3;              // 0..3
    const int a_row_l = ((a_tile & 1) << 3) + (lane & 7);
    const int a_ktile = a_tile >> 1;           // 0..1 (16B half of 32B k-step)
    const int b_khalf = (lane >> 3) & 1;
    const int b_row_l = (((lane >> 4) & 1) << 3) + (lane & 7);

    const uint32_t a_warp_off = (uint32_t)(warp_m * 64) * 128u;
    const uint32_t b_warp_off = A_BYTES + (uint32_t)(warp_n * 64) * 128u;

    float c[4][8][4];
    #pragma unroll
    for (int mi = 0; mi < 4; ++mi)
        #pragma unroll
        for (int ni = 0; ni < 8; ++ni)
            #pragma unroll
            for (int q = 0; q < 4; ++q) c[mi][ni][q] = 0.0f;

    uint32_t af[2][4][4];   // [pingpong][mi][frag]
    uint32_t bf[2][4][4];   // [pingpong][ni2][frag]

    // ks = 0..3: k16 step within the 64-fp16 (128B) stage row.
    auto load_frags = [&](uint32_t st, int ks, int pb) {
        const uint32_t abw = st + a_warp_off;
        const uint32_t bbw = st + b_warp_off;
        #pragma unroll
        for (int mi = 0; mi < 4; ++mi) {
            int row = mi * 16 + a_row_l;
            uint32_t off = (uint32_t)((ks * 2 + a_ktile) * 16) ^
                           ((uint32_t)(row & 7) << 4);
            ldsm4(af[pb][mi], abw + (uint32_t)row * 128u + off);
        }
        #pragma unroll
        for (int ni2 = 0; ni2 < 4; ++ni2) {
            int n = ni2 * 16 + b_row_l;
            uint32_t off = (uint32_t)((ks * 2 + b_khalf) * 16) ^
                           ((uint32_t)(n & 7) << 4);
            ldsm4(bf[pb][ni2], bbw + (uint32_t)n * 128u + off);
        }
    };

    auto mma_group = [&](int pb) {
        #pragma unroll
        for (int mi = 0; mi < 4; ++mi)
            #pragma unroll
            for (int ni = 0; ni < 8; ++ni) {
                const uint32_t* bp = &bf[pb][ni >> 1][(ni & 1) * 2];
                mma_f16(c[mi][ni], af[pb][mi], bp[0], bp[1]);
            }
    };

    // prologue: fill 3 stages, land frags for stage 0 / ks 0
    issue(0, 0); issue(1, 1); issue(2, 2);
    cp_wait<2>();
    __syncthreads();
    load_frags(sb, 0, 0);

    #pragma unroll 4
    for (int it = 0; it < NKIT; ++it) {
        const uint32_t st = sb + (uint32_t)(it & 3) * STAGE_BYTES;

        // entry invariant: pb0 holds ks0 frags of stage it
        load_frags(st, 1, 1);                 // ks1 -> pb1
        mma_group(0);                         // ks0

        if (it + 3 < NKIT) issue(it + 3, (uint32_t)((it + 3) & 3));
        else cp_commit();                     // keep group numbering advancing

        load_frags(st, 2, 0);                 // ks2 -> pb0
        mma_group(1);                         // ks1
        load_frags(st, 3, 1);                 // ks3 -> pb1
        mma_group(0);                         // ks2 queued UNDER the barrier

        cp_wait<2>();                         // stage it+1 landed
        __syncthreads();                      // cross-thread visibility + reuse

        if (it + 1 < NKIT)
            load_frags(sb + (uint32_t)((it + 1) & 3) * STAGE_BYTES, 0, 0);
        mma_group(1);                         // ks3
    }

    // ---- epilogue: streaming stores (evict-first; out never re-read) ----
    const int g = lane >> 2, t4 = lane & 3;
    const int row0 = m_base + warp_m * 64 + g;
    const int col0 = o * 256 + warp_n * 64 + t4 * 2;
    #pragma unroll
    for (int mi = 0; mi < 4; ++mi) {
        #pragma unroll
        for (int ni = 0; ni < 8; ++ni) {
            float* p0 = out + (size_t)(row0 + mi * 16) * 4096 + col0 + ni * 8;
            float* p1 = p0 + 8 * 4096;
            stg_cs_v2(p0, c[mi][ni][0], c[mi][ni][1]);
            stg_cs_v2(p1, c[mi][ni][2], c[mi][ni][3]);
        }
    }
}

// ---------------------------------------------------------------------------
extern "C" void kernel_launch(void* const* d_in, const int* in_sizes, int n_in,
                              void* d_out, int out_size) {
    const float* x  = (const float*)d_in[0];
    const float* w  = (const float*)d_in[1];
    const int*   fi = (const int*)d_in[2];
    float* out = (float*)d_out;

    convert_kernel<<<8192, 256>>>(x);
    repack_kernel<<<dim3(8, 8, 80), dim3(32, 8)>>>(w, fi);

    cudaFuncSetAttribute(gemm_kernel,
                         cudaFuncAttributeMaxDynamicSharedMemorySize, SMEM_TOTAL);
    gemm_kernel<<<dim3(16, 64), 256, SMEM_TOTAL>>>(fi, out);
}

// round 17
// speedup vs baseline: 1.0406x; 1.0170x over previous
#include <cuda_runtime.h>
#include <cuda_fp16.h>
#include <cstdint>

// ============================================================================
// SharedMatrix (butterfly block-sparse matmul) on GB300, PLAIN sm_103 target.
//   x : [8192, 4096] f32          (d_in[0])
//   w : [4096, 5, 256] f32        (d_in[1])
//   fi: [16, 5] int32             (d_in[2])
//   out:[8192, 4096] f32
//
// 16 GEMMs: M=8192, N=256, K=1280, fp16 mma.sync.m16n8k16 (f32 accum).
// R17 = R16 with two fixes:
//   (1) convert_kernel covered only HALF of each 16KB A image (j<8 -> j<16);
//       zero rows 64-127 explained rel_err = sqrt(0.5) = 0.707 exactly.
//   (2) mbarrier consumer wait restored to .acquire.cta.shared::cta form
//       (async-proxy bulk writes -> generic-proxy ldmatrix reads need acquire).
// Producers: 2 cp.async.bulk + mbarrier per stage issued by tid0 (kills the
// 3072-op cp.async issue stream that was co-binding with the tensor pipe).
// ============================================================================

static constexpr int NKIT = 20;                    // 5 blocks x 4 chunks of k=64
static constexpr uint32_t A_BYTES = 16384;         // 128 x 64 x 2 (swizzled img)
static constexpr uint32_t B_BYTES = 32768;         // 256 x 64 x 2 (swizzled img)
static constexpr uint32_t STAGE_BYTES = A_BYTES + B_BYTES;      // 48KB
static constexpr uint32_t SMEM_TOTAL = 4 * STAGE_BYTES + 1024;  // 197632

// x as fp16 pre-swizzled 16KB images: g_Xt[(mt*64 + kc)*4096 + swz/4]
//   image (mt, kc): rows r=0..127 (m = mt*128+r), cols c=0..63 (k = kc*64+c)
__device__ uint32_t g_Xt[64u * 64u * 4096u];       // 64 MB
// Repacked gathered fp16 weights, pre-swizzled 32KB SMEM images:
// image (o, c64): [n=256][k=64] fp16, swz(n*128 + kk*2).  16*20*32KB = 10.5MB
__device__ uint32_t g_Bp[16 * NKIT * 8192];

// ---------------------------------------------------------------------------
__device__ __forceinline__ uint32_t h2_bits(__half2 h) {
    union { __half2 h; uint32_t u; } cvt;
    cvt.h = h;
    return cvt.u;
}
__device__ __forceinline__ uint32_t smem_u32(const void* p) {
    uint32_t a;
    asm("{ .reg .u64 t; cvta.to.shared.u64 t, %1; cvt.u32.u64 %0, t; }"
        : "=r"(a) : "l"(p));
    return a;
}
__device__ __forceinline__ void mbar_init(uint32_t mbar, uint32_t count) {
    asm volatile("mbarrier.init.shared.b64 [%0], %1;"
                 :: "r"(mbar), "r"(count) : "memory");
}
__device__ __forceinline__ void mbar_expect_tx(uint32_t mbar, uint32_t bytes) {
    asm volatile("mbarrier.arrive.expect_tx.shared.b64 _, [%0], %1;"
                 :: "r"(mbar), "r"(bytes) : "memory");
}
__device__ __forceinline__ void mbar_wait(uint32_t mbar, uint32_t parity) {
    asm volatile(
        "{\n\t.reg .pred P1;\n\t"
        "LAB_WAIT_%=:\n\t"
        "mbarrier.try_wait.parity.acquire.cta.shared::cta.b64 P1, [%0], %1;\n\t"
        "@P1 bra.uni LAB_DONE_%=;\n\t"
        "bra.uni LAB_WAIT_%=;\n\t"
        "LAB_DONE_%=:\n\t}"
        :: "r"(mbar), "r"(parity) : "memory");
}
__device__ __forceinline__ void bulk_g2s(uint32_t dst, const void* src,
                                         uint32_t bytes, uint32_t mbar) {
    asm volatile(
        "cp.async.bulk.shared::cta.global.mbarrier::complete_tx::bytes "
        "[%0], [%1], %2, [%3];"
        :: "r"(dst), "l"(src), "r"(bytes), "r"(mbar) : "memory");
}
__device__ __forceinline__ void ldsm4(uint32_t* r, uint32_t a) {
    asm volatile("ldmatrix.sync.aligned.m8n8.x4.shared.b16 {%0,%1,%2,%3}, [%4];"
                 : "=r"(r[0]), "=r"(r[1]), "=r"(r[2]), "=r"(r[3]) : "r"(a));
}
__device__ __forceinline__ void mma_f16(float* c, const uint32_t* a,
                                        uint32_t b0, uint32_t b1) {
    asm volatile(
        "mma.sync.aligned.m16n8k16.row.col.f32.f16.f16.f32 "
        "{%0,%1,%2,%3}, {%4,%5,%6,%7}, {%8,%9}, {%0,%1,%2,%3};"
        : "+f"(c[0]), "+f"(c[1]), "+f"(c[2]), "+f"(c[3])
        : "r"(a[0]), "r"(a[1]), "r"(a[2]), "r"(a[3]), "r"(b0), "r"(b1));
}
__device__ __forceinline__ void stg_cs_v2(float* p, float v0, float v1) {
    asm volatile("st.global.cs.v2.f32 [%0], {%1, %2};"
                 :: "l"(p), "f"(v0), "f"(v1) : "memory");
}

// ---------------------------------------------------------------------------
// convert: x f32 -> fp16 pre-swizzled 16KB images in g_Xt.
//   grid: 4096 = (kc 64) | (mt 64 << 6), block 256.
//   Each image = 4096 u32 -> 16 iterations x 256 threads.
// ---------------------------------------------------------------------------
__global__ void __launch_bounds__(256, 4)
convert_kernel(const float* __restrict__ x) {
    const int kc = (int)blockIdx.x & 63;
    const int mt = (int)blockIdx.x >> 6;
    uint32_t* img = g_Xt + ((size_t)mt * 64 + kc) * 4096;
    const int t = (int)threadIdx.x;
    #pragma unroll
    for (int j = 0; j < 16; ++j) {      // FIX: full 4096 u32 (was 8 -> half)
        int idx = j * 256 + t;          // 0..4095 (u32 units)
        int r = idx >> 5;               // row 0..127
        int c2 = idx & 31;              // u32 col 0..31
        const float2 v = *reinterpret_cast<const float2*>(
            x + (size_t)(mt * 128 + r) * 4096 + kc * 64 + c2 * 2);
        uint32_t val = h2_bits(__floats2half2_rn(v.x, v.y));
        uint32_t off = (uint32_t)r * 128u + (uint32_t)c2 * 4u;
        uint32_t swz = off ^ ((off >> 3) & 0x70u);
        img[swz >> 2] = val;
    }
}

// ---------------------------------------------------------------------------
// repack: gather + transpose + fp16(RN) weights into pre-swizzled images
//   grid: (ntile=8, kchunk32=8, o*5+a=80), block (32, 8)
// image (o, c64 = a*4 + (c32>>1)), k base within image = (c32&1)*32
// ---------------------------------------------------------------------------
__global__ void __launch_bounds__(256, 4)
repack_kernel(const float* __restrict__ w, const int* __restrict__ fi) {
    const int oa = blockIdx.z;
    const int o = oa / 5, a = oa % 5;
    const int f = fi[o * 5 + a];
    const int g = f / 5, slot = f % 5;
    const int k0 = blockIdx.y * 32;
    const int n0 = blockIdx.x * 32;
    const int c32 = blockIdx.y;

    __shared__ float t[32][33];
    const int tx = threadIdx.x, ty = threadIdx.y;

    #pragma unroll
    for (int i = 0; i < 4; ++i) {
        int k = ty + i * 8;
        t[k][tx] = w[((size_t)(g * 256 + k0 + k) * 5 + slot) * 256 + n0 + tx];
    }
    __syncthreads();

    uint32_t* tile = g_Bp +
        ((size_t)o * NKIT + a * 4 + (c32 >> 1)) * 8192;
    const int kb = (c32 & 1) * 32;
    const int tid = ty * 32 + tx;
    const int p  = tid & 15;        // k pair index 0..15 (2 fp16 each)
    const int nn = tid >> 4;        // 0..15
    #pragma unroll
    for (int i = 0; i < 2; ++i) {
        int n = n0 + nn + i * 16;
        uint32_t val = h2_bits(
            __floats2half2_rn(t[2 * p][nn + i * 16], t[2 * p + 1][nn + i * 16]));
        uint32_t off = (uint32_t)n * 128u + (uint32_t)(kb + 2 * p) * 2u;
        uint32_t swz = off ^ ((off >> 3) & 0x70u);
        tile[swz >> 2] = val;
    }
}

// ---------------------------------------------------------------------------
// GEMM: grid (o=16, mtile=64), 256 threads, CTA tile 128(M) x 256(N)
//   8 warps in 2(m) x 4(n) grid of 64x64 warp tiles; fp16 m16n8k16;
//   k=64 per stage; producer = tid0 with 2 cp.async.bulk + mbarrier/stage.
// ---------------------------------------------------------------------------
__global__ void __launch_bounds__(256, 1)
gemm_kernel(const int* __restrict__ fi, float* __restrict__ out) {
    extern __shared__ char smem_raw[];
    __shared__ uint64_t bars_s[4];
    const uint32_t sb = (smem_u32(smem_raw) + 1023u) & ~1023u;
    const uint32_t bar0 = smem_u32(bars_s);
    const int tid = (int)threadIdx.x;
    const int wid = tid >> 5;
    const int lane = tid & 31;
    const int o = (int)blockIdx.x;
    const int mt = (int)blockIdx.y;
    const int m_base = mt * 128;
    const int warp_m = wid >> 2;   // 0..1  (64 rows each)
    const int warp_n = wid & 3;    // 0..3  (64 cols each)

    int kcb[5];                    // A image kc base per a-block: g*4
    #pragma unroll
    for (int a = 0; a < 5; ++a) kcb[a] = (fi[o * 5 + a] / 5) * 4;

    if (tid == 0) {
        #pragma unroll
        for (int s = 0; s < 4; ++s) mbar_init(bar0 + 8u * s, 1);
    }
    __syncthreads();

    const uint32_t* asrc0 = g_Xt + (size_t)mt * 64 * 4096;
    const uint32_t* bsrc0 = g_Bp + (size_t)o * NKIT * 8192;

    auto issue = [&](int it) {
        if (tid == 0) {
            const uint32_t s = (uint32_t)(it & 3);
            const uint32_t bar = bar0 + 8u * s;
            const uint32_t st = sb + s * STAGE_BYTES;
            mbar_expect_tx(bar, STAGE_BYTES);
            bulk_g2s(st, asrc0 + (size_t)(kcb[it >> 2] + (it & 3)) * 4096,
                     A_BYTES, bar);
            bulk_g2s(st + A_BYTES, bsrc0 + (size_t)it * 8192, B_BYTES, bar);
        }
    };

    // ---- consumer lane addressing ----
    const int a_tile = lane >> 3;              // 0..3
    const int a_row_l = ((a_tile & 1) << 3) + (lane & 7);
    const int a_ktile = a_tile >> 1;           // 0..1 (16B half of 32B k-step)
    const int b_khalf = (lane >> 3) & 1;
    const int b_row_l = (((lane >> 4) & 1) << 3) + (lane & 7);

    const uint32_t a_warp_off = (uint32_t)(warp_m * 64) * 128u;
    const uint32_t b_warp_off = A_BYTES + (uint32_t)(warp_n * 64) * 128u;

    float c[4][8][4];
    #pragma unroll
    for (int mi = 0; mi < 4; ++mi)
        #pragma unroll
        for (int ni = 0; ni < 8; ++ni)
            #pragma unroll
            for (int q = 0; q < 4; ++q) c[mi][ni][q] = 0.0f;

    uint32_t af[2][4][4];   // [pingpong][mi][frag]
    uint32_t bf[2][4][4];   // [pingpong][ni2][frag]

    // ks = 0..3: k16 step within the 64-fp16 (128B) stage row.
    auto load_frags = [&](uint32_t st, int ks, int pb) {
        const uint32_t abw = st + a_warp_off;
        const uint32_t bbw = st + b_warp_off;
        #pragma unroll
        for (int mi = 0; mi < 4; ++mi) {
            int row = mi * 16 + a_row_l;
            uint32_t off = (uint32_t)((ks * 2 + a_ktile) * 16) ^
                           ((uint32_t)(row & 7) << 4);
            ldsm4(af[pb][mi], abw + (uint32_t)row * 128u + off);
        }
        #pragma unroll
        for (int ni2 = 0; ni2 < 4; ++ni2) {
            int n = ni2 * 16 + b_row_l;
            uint32_t off = (uint32_t)((ks * 2 + b_khalf) * 16) ^
                           ((uint32_t)(n & 7) << 4);
            ldsm4(bf[pb][ni2], bbw + (uint32_t)n * 128u + off);
        }
    };

    auto mma_group = [&](int pb) {
        #pragma unroll
        for (int mi = 0; mi < 4; ++mi)
            #pragma unroll
            for (int ni = 0; ni < 8; ++ni) {
                const uint32_t* bp = &bf[pb][ni >> 1][(ni & 1) * 2];
                mma_f16(c[mi][ni], af[pb][mi], bp[0], bp[1]);
            }
    };

    // prologue: fill 3 stages, land frags for stage 0 / ks 0
    issue(0); issue(1); issue(2);
    mbar_wait(bar0, 0);
    __syncthreads();
    load_frags(sb, 0, 0);

    #pragma unroll 4
    for (int it = 0; it < NKIT; ++it) {
        const uint32_t st = sb + (uint32_t)(it & 3) * STAGE_BYTES;

        // entry invariant: pb0 holds ks0 frags of stage it
        load_frags(st, 1, 1);                 // ks1 -> pb1
        mma_group(0);                         // ks0

        if (it + 3 < NKIT) issue(it + 3);     // stage consumed before last
                                              // __syncthreads -> safe overwrite
        load_frags(st, 2, 0);                 // ks2 -> pb0
        mma_group(1);                         // ks1
        load_frags(st, 3, 1);                 // ks3 -> pb1
        mma_group(0);                         // ks2 queued UNDER the wait

        if (it + 1 < NKIT)
            mbar_wait(bar0 + 8u * ((it + 1) & 3),
                      (uint32_t)(((it + 1) >> 2) & 1));
        __syncthreads();                      // reuse ordering across threads

        if (it + 1 < NKIT)
            load_frags(sb + (uint32_t)((it + 1) & 3) * STAGE_BYTES, 0, 0);
        mma_group(1);                         // ks3
    }

    // ---- epilogue: streaming stores (evict-first; out never re-read) ----
    const int g = lane >> 2, t4 = lane & 3;
    const int row0 = m_base + warp_m * 64 + g;
    const int col0 = o * 256 + warp_n * 64 + t4 * 2;
    #pragma unroll
    for (int mi = 0; mi < 4; ++mi) {
        #pragma unroll
        for (int ni = 0; ni < 8; ++ni) {
            float* p0 = out + (size_t)(row0 + mi * 16) * 4096 + col0 + ni * 8;
            float* p1 = p0 + 8 * 4096;
            stg_cs_v2(p0, c[mi][ni][0], c[mi][ni][1]);
            stg_cs_v2(p1, c[mi][ni][2], c[mi][ni][3]);
        }
    }
}

// ---------------------------------------------------------------------------
extern "C" void kernel_launch(void* const* d_in, const int* in_sizes, int n_in,
                              void* d_out, int out_size) {
    const float* x  = (const float*)d_in[0];
    const float* w  = (const float*)d_in[1];
    const int*   fi = (const int*)d_in[2];
    float* out = (float*)d_out;

    convert_kernel<<<4096, 256>>>(x);
    repack_kernel<<<dim3(8, 8, 80), dim3(32, 8)>>>(w, fi);

    cudaFuncSetAttribute(gemm_kernel,
                         cudaFuncAttributeMaxDynamicSharedMemorySize, SMEM_TOTAL);
    gemm_kernel<<<dim3(16, 64), 256, SMEM_TOTAL>>>(fi, out);
}